// round 5
// baseline (speedup 1.0000x reference)
#include <cuda_runtime.h>

#define BB 1024
#define TT 2048
#define DD 16
#define UU 4
#define HH 128
#define MG 4            // batch rows per group
#define NT 1024         // threads per CTA, two groups of 512
#define INP 28          // sINt row pitch (floats)
#define H2P 132         // sH2 / sW2T row pitch
#define H1P 68          // sH1 per-kq-slice pitch (floats): 16*4 + 4 skew

typedef unsigned long long u64;

__device__ __forceinline__ u64 pk2(float lo, float hi) {
    u64 r; asm("mov.b64 %0, {%1, %2};" : "=l"(r) : "f"(lo), "f"(hi)); return r;
}
__device__ __forceinline__ void upk2(u64 v, float& lo, float& hi) {
    asm("mov.b64 {%0, %1}, %2;" : "=f"(lo), "=f"(hi) : "l"(v));
}
__device__ __forceinline__ u64 ffma2(u64 a, u64 b, u64 c) {
    u64 d; asm("fma.rn.f32x2 %0, %1, %2, %3;" : "=l"(d) : "l"(a), "l"(b), "l"(c)); return d;
}
__device__ __forceinline__ u64 add2(u64 a, u64 b) {
    u64 c; asm("add.rn.f32x2 %0, %1, %2;" : "=l"(c) : "l"(a), "l"(b)); return c;
}
__device__ __forceinline__ float tanh_fast(float x) {
    float y; asm("tanh.approx.f32 %0, %1;" : "=f"(y) : "f"(x)); return y;
}
__device__ __forceinline__ u64 shfl_xor64(u64 v, int mask) {
    unsigned lo = (unsigned)v, hi = (unsigned)(v >> 32);
    lo = __shfl_xor_sync(0xffffffffu, lo, mask);
    hi = __shfl_xor_sync(0xffffffffu, hi, mask);
    return ((u64)hi << 32) | (u64)lo;
}
__device__ __forceinline__ void gbar(int g) {
    asm volatile("bar.sync %0, %1;" :: "r"(g + 1), "r"(512) : "memory");
}

__global__ void __launch_bounds__(NT, 1)
gnsde_kernel(const float* __restrict__ carry,
             const float* __restrict__ x,
             const float* __restrict__ noise,
             const float* __restrict__ W0,
             const float* __restrict__ b0,
             const float* __restrict__ W1,
             const float* __restrict__ b1,
             const float* __restrict__ W2,
             const float* __restrict__ b2,
             float* __restrict__ out)
{
    __shared__ __align__(16) u64   sW0p[((DD + UU) / 2) * HH]; // k-pair packed W0  (10 KB)
    __shared__ __align__(16) float sW2T[DD * H2P];             // [d][k]            (8.4 KB)
    __shared__ __align__(16) float sH1[2][8 * H1P];            // per-group, kq-sliced
    __shared__ __align__(16) float sH2[2][MG * H2P];           // per-group [m][j]
    __shared__ __align__(16) float sINt[2][MG * INP];          // per-group [m][k]; 0..15=y, 16..19=x

    const int tid = threadIdx.x;
    const int g   = tid >> 9;          // group 0/1
    const int gt  = tid & 511;         // thread id within group
    const int brow = blockIdx.x * (2 * MG) + g * MG;

    // layer-0 identity: (j0, m0)
    const int j0 = gt >> 2;
    const int m0 = gt & 3;
    // layer-1 identity: (jp, kq) — k-split 8-way intra-warp
    const int jp = gt >> 3;
    const int kq = gt & 7;
    // layer-2 identity: (md, kq2) — same partition shape
    const int md  = gt >> 3;
    const int kq2 = gt & 7;
    const int m2  = md >> 4;
    const int d2  = md & 15;

    // ---- persistent registers (kept small: <=64 reg budget) ----
    float w1r0[16], w1r1[16];
#pragma unroll
    for (int kk = 0; kk < 16; ++kk) {
        w1r0[kk] = W1[(kq * 16 + kk) * HH + 2 * jp];
        w1r1[kk] = W1[(kq * 16 + kk) * HH + 2 * jp + 1];
    }
    const float b0j = b0[j0];
    const float b1v = b1[2 * jp + (kq >> 2)];
    const float b2v = b2[d2];
    float yreg = carry[(size_t)(brow + m2) * DD + d2];  // used on kq2==0 lanes

    // ---- stage shared ----
    for (int idx = tid; idx < ((DD + UU) / 2) * HH; idx += NT) {
        int kk2 = idx >> 7, jj = idx & 127;
        sW0p[idx] = pk2(W0[(2 * kk2) * HH + jj], W0[(2 * kk2 + 1) * HH + jj]);
    }
    for (int idx = tid; idx < HH * DD; idx += NT) {
        int i = idx >> 4, d = idx & 15;
        sW2T[d * H2P + i] = W2[idx];
    }
    if (kq2 == 0) sINt[g][m2 * INP + d2] = yreg;
    if (gt >= 504) {   // gt 504..511; use first 4 for x staging
        int m = gt - 504;
        if (m < MG) {
            float4 xv = *(const float4*)&x[((size_t)(brow + m) * TT) * UU];
            *(float4*)&sINt[g][m * INP + DD] = xv;
        }
    }
    __syncthreads();

    const float alpha = 0.1f;
    const float onema = 0.9f;
    const float sqa   = 0.31622776601683794f;

    float* ys  = out;
    float* mts = out + (size_t)BB * TT * DD;
    float* mus = out + 2ull * BB * TT * DD;

    for (int t = 0; t < TT; ++t) {
        // ---- prefetch globals ----
        float nz = 0.0f;
        if (kq2 == 0) nz = noise[((size_t)(brow + m2) * TT + t) * DD + d2];
        float4 xn = make_float4(0.f, 0.f, 0.f, 0.f);
        const bool xp = (gt >= 504 && gt < 504 + MG) && (t + 1 < TT);
        if (xp) xn = *(const float4*)&x[((size_t)(brow + (gt - 504)) * TT + (t + 1)) * UU];

        // ===== layer 0: thread (j0, m0) =====
        {
            u64 a0 = 0, a1 = 0;
            const float* rp = &sINt[g][m0 * INP];
#pragma unroll
            for (int i = 0; i < 5; ++i) {
                ulonglong2 h = *(const ulonglong2*)&rp[4 * i];
                a0 = ffma2(sW0p[(2 * i)     * HH + j0], h.x, a0);
                a1 = ffma2(sW0p[(2 * i + 1) * HH + j0], h.y, a1);
            }
            float lo, hi; upk2(add2(a0, a1), lo, hi);
            sH1[g][(j0 >> 4) * H1P + (j0 & 15) * 4 + m0] = tanh_fast(lo + hi + b0j);
        }
        gbar(g);

        // ===== layer 1: thread (jp, kq); 2 j's, 16-k slice, 4 m =====
        {
            u64 A0 = 0, A1 = 0, A2 = 0, A3 = 0;
            const float* hb = &sH1[g][kq * H1P];
#pragma unroll
            for (int kk = 0; kk < 16; ++kk) {
                ulonglong2 hh = *(const ulonglong2*)&hb[kk * 4];   // m0..3 at this k
                u64 w0d = pk2(w1r0[kk], w1r0[kk]);
                u64 w1d = pk2(w1r1[kk], w1r1[kk]);
                A0 = ffma2(w0d, hh.x, A0);  A1 = ffma2(w0d, hh.y, A1);
                A2 = ffma2(w1d, hh.x, A2);  A3 = ffma2(w1d, hh.y, A3);
            }
            // index-halving butterfly over the 8-way k-split
            const bool s4 = (kq & 4) != 0;
            u64 B0 = s4 ? A2 : A0, X0 = s4 ? A0 : A2;   // keep j by bit2
            u64 B1 = s4 ? A3 : A1, X1 = s4 ? A1 : A3;
            B0 = add2(B0, shfl_xor64(X0, 4));
            B1 = add2(B1, shfl_xor64(X1, 4));
            const bool s2 = (kq & 2) != 0;
            u64 C = s2 ? B1 : B0, XC = s2 ? B0 : B1;    // keep m-half by bit1
            C = add2(C, shfl_xor64(XC, 2));
            C = add2(C, shfl_xor64(C, 1));              // same identity pair
            if ((kq & 1) == 0) {
                float lo, hi; upk2(C, lo, hi);
                lo = tanh_fast(lo + b1v);
                hi = tanh_fast(hi + b1v);
                const int jw = 2 * jp + (kq >> 2);
                const int mA = (kq & 2);                 // 0 or 2
                sH2[g][mA * H2P + jw]       = lo;
                sH2[g][(mA + 1) * H2P + jw] = hi;
            }
        }
        gbar(g);

        // ===== layer 2 + gate: thread (md=(m2,d2), kq2) =====
        {
            u64 aA = 0, aB = 0;
            const float* hr = &sH2[g][m2 * H2P + kq2 * 16];
            const float* wr = &sW2T[d2 * H2P + kq2 * 16];
#pragma unroll
            for (int i = 0; i < 4; ++i) {
                ulonglong2 hp = *(const ulonglong2*)&hr[4 * i];
                ulonglong2 wp = *(const ulonglong2*)&wr[4 * i];
                aA = ffma2(hp.x, wp.x, aA);
                aB = ffma2(hp.y, wp.y, aB);
            }
            u64 s = add2(aA, aB);
            s = add2(s, shfl_xor64(s, 1));
            s = add2(s, shfl_xor64(s, 2));
            s = add2(s, shfl_xor64(s, 4));
            if (kq2 == 0) {
                float lo, hi; upk2(s, lo, hi);
                float mt = lo + hi + b2v;
                float mu = onema * yreg + alpha * mt;
                float yn = mu + sqa * nz;
                size_t base = ((size_t)(brow + m2) * TT + t) * DD + d2;
                ys[base]  = yn;
                mts[base] = mt;
                mus[base] = mu;
                yreg = yn;
                sINt[g][m2 * INP + d2] = yn;
            }
            if (xp) {
                int m = gt - 504;
                *(float4*)&sINt[g][m * INP + DD] = xn;
            }
        }
        gbar(g);
    }
}

extern "C" void kernel_launch(void* const* d_in, const int* in_sizes, int n_in,
                              void* d_out, int out_size) {
    const float* carry = (const float*)d_in[0];
    const float* x     = (const float*)d_in[1];
    const float* noise = (const float*)d_in[2];
    const float* W0    = (const float*)d_in[3];
    const float* b0    = (const float*)d_in[4];
    const float* W1    = (const float*)d_in[5];
    const float* b1    = (const float*)d_in[6];
    const float* W2    = (const float*)d_in[7];
    const float* b2    = (const float*)d_in[8];
    float* out = (float*)d_out;

    gnsde_kernel<<<BB / (2 * MG), NT>>>(carry, x, noise, W0, b0, W1, b1, W2, b2, out);
}